// round 13
// baseline (speedup 1.0000x reference)
#include <cuda_runtime.h>
#include <cuda_fp16.h>
#include <cstdint>

#define B_    1024
#define T_    512
#define OBS_  64
#define H_    256
#define A_    16

// ---------- helpers ----------
__device__ __forceinline__ uint32_t f2h2(float lo, float hi) {
    uint32_t r;
    asm("cvt.rn.f16x2.f32 %0, %1, %2;" : "=r"(r) : "f"(hi), "f"(lo));
    return r;
}
__device__ __forceinline__ float sigf(float x) {
    float t;
    asm("tanh.approx.f32 %0, %1;" : "=f"(t) : "f"(0.5f * x));
    return fmaf(0.5f, t, 0.5f);
}
// m16n8k16 row.col f32 += f16*f16
__device__ __forceinline__ void mma16816(float* c, const uint32_t* a,
                                         uint32_t b0, uint32_t b1) {
    asm("mma.sync.aligned.m16n8k16.row.col.f32.f16.f16.f32 "
        "{%0,%1,%2,%3}, {%4,%5,%6,%7}, {%8,%9}, {%0,%1,%2,%3};"
        : "+f"(c[0]), "+f"(c[1]), "+f"(c[2]), "+f"(c[3])
        : "r"(a[0]), "r"(a[1]), "r"(a[2]), "r"(a[3]), "r"(b0), "r"(b1));
}

// ============================================================================
// Persistent RNN kernel. 128 CTAs x 256 thr (8 warps). CTA owns 8 batch rows.
// Single barrier per step; o pipelined 2 deep:
//   iter t:  h-GEMM(h_{t-1}) -> h_t               (all warps, j-split)
//            o-partials(h_{t-1}) -> s_os[cur]     (output index t-1)
//            warp0: reduce s_os[nxt] -> out[t-2]  (off critical path)
//            one __syncthreads()
// B operands stored in FRAGMENT ORDER: per (k-tile kt, quad-row q, col b) a
// uint2 { k rows 2q,2q+1 | 2q+8,2q+9 } -> one LDS.64 per tile per thread.
//   u32 idx (j', b):  kt=j'>>4, r=j'&15 : ((kt*4+(r&7)/2)*8+b)*2+(r>>3), half r&1
// ============================================================================
extern "C" __global__ void __launch_bounds__(256, 1)
rnn_kernel(const float* __restrict__ obs,  const float* __restrict__ W_in,
           const float* __restrict__ W_h,  const float* __restrict__ b_h,
           const float* __restrict__ W_out, const float* __restrict__ b_out,
           float* __restrict__ out)
{
    __shared__ uint32_t s_hp[2][1024];     // h   frags [buf][((kt*4+q)*8+b)*2+ws]
    __shared__ uint32_t s_ob[2][256];      // obs frags [buf][...] kt=0..3
    __shared__ float    s_os[2][8][128];   // o partials [buf][warp][a*8+b]

    const int tid  = threadIdx.x;
    const int w    = tid >> 5, lane = tid & 31;
    const int ln   = lane >> 2, lq = lane & 3;     // groupID / inGroup
    const int jbase = w * 32 + ln;
    const int bg0  = blockIdx.x * 8;

    // ---- persistent A-fragments: W_h [2 m-tiles][16 k-tiles][4 regs] ----
    uint32_t ah[2][16][4];
#pragma unroll
    for (int kt = 0; kt < 16; kt++) {
        const int k0 = kt * 16 + lq * 2;
#pragma unroll
        for (int m = 0; m < 2; m++) {
            const int r0 = jbase + m * 16, r1 = r0 + 8;
            float2 v00 = *(const float2*)&W_h[r0 * 256 + k0];
            float2 v10 = *(const float2*)&W_h[r1 * 256 + k0];
            float2 v01 = *(const float2*)&W_h[r0 * 256 + k0 + 8];
            float2 v11 = *(const float2*)&W_h[r1 * 256 + k0 + 8];
            ah[m][kt][0] = f2h2(v00.x, v00.y);
            ah[m][kt][1] = f2h2(v10.x, v10.y);
            ah[m][kt][2] = f2h2(v01.x, v01.y);
            ah[m][kt][3] = f2h2(v11.x, v11.y);
        }
    }
    // ---- W_in fragments [2][4][4] ----
    uint32_t ai[2][4][4];
#pragma unroll
    for (int kt = 0; kt < 4; kt++) {
        const int k0 = kt * 16 + lq * 2;
#pragma unroll
        for (int m = 0; m < 2; m++) {
            const int r0 = jbase + m * 16, r1 = r0 + 8;
            float2 v00 = *(const float2*)&W_in[r0 * 64 + k0];
            float2 v10 = *(const float2*)&W_in[r1 * 64 + k0];
            float2 v01 = *(const float2*)&W_in[r0 * 64 + k0 + 8];
            float2 v11 = *(const float2*)&W_in[r1 * 64 + k0 + 8];
            ai[m][kt][0] = f2h2(v00.x, v00.y);
            ai[m][kt][1] = f2h2(v10.x, v10.y);
            ai[m][kt][2] = f2h2(v01.x, v01.y);
            ai[m][kt][3] = f2h2(v11.x, v11.y);
        }
    }
    // ---- W_out fragments: k-tiles 2w, 2w+1 ----
    uint32_t ao[2][4];
#pragma unroll
    for (int i = 0; i < 2; i++) {
        const int k0 = (w * 2 + i) * 16 + lq * 2;
        float2 v00 = *(const float2*)&W_out[ln * 256 + k0];
        float2 v10 = *(const float2*)&W_out[(ln + 8) * 256 + k0];
        float2 v01 = *(const float2*)&W_out[ln * 256 + k0 + 8];
        float2 v11 = *(const float2*)&W_out[(ln + 8) * 256 + k0 + 8];
        ao[i][0] = f2h2(v00.x, v00.y);
        ao[i][1] = f2h2(v10.x, v10.y);
        ao[i][2] = f2h2(v01.x, v01.y);
        ao[i][3] = f2h2(v11.x, v11.y);
    }

    float bh[4];
#pragma unroll
    for (int ri = 0; ri < 4; ri++) bh[ri] = b_h[jbase + 8 * ri];
    const float bo = (w == 0) ? b_out[lane >> 1] : 0.0f;

    // EMA state (fp32, exact)
    float hs[4][2];
#pragma unroll
    for (int ri = 0; ri < 4; ri++) { hs[ri][0] = 0.0f; hs[ri][1] = 0.0f; }
    float oreg[4] = {0.0f, 0.0f, 0.0f, 0.0f};

    // zero h buffers (h_{-1}=0); preload obs(0) into buf 0
#pragma unroll
    for (int i = 0; i < 8; i++)
        ((uint32_t*)s_hp)[tid + i * 256] = 0u;
    {
        // writer identity: b = tid&7, pair pk = tid>>3 covers k rows 2pk,2pk+1
        const int b = tid & 7, pk = tid >> 3;
        float2 v = *(const float2*)&obs[((size_t)(bg0 + b) * T_) * OBS_ + pk * 2];
        const int kt = pk >> 3, q = pk & 3, ws = (pk >> 2) & 1;
        s_ob[0][((kt * 4 + q) * 8 + b) * 2 + ws] = f2h2(v.x, v.y);
    }
    __syncthreads();

    const int pb = tid & 7, pk = tid >> 3;         // obs prefetch identity
    const int okt = pk >> 3, oq = pk & 3, ows = (pk >> 2) & 1;
    // epilogue store geometry (per ri): kt = w*2 + (ri>>1), ws = ri&1,
    // q = ln>>1, half = ln&1
    const int eq = ln >> 1, ehalf = ln & 1;

    for (int t = 0; t < T_ + 2; t++) {
        const int cur = t & 1, nxt = cur ^ 1;

        // ---- warp 0: reduce previous partials -> out[t-2] (off crit path) ----
        if (w == 0 && t >= 2) {
            float4 s = make_float4(0.f, 0.f, 0.f, 0.f);
#pragma unroll
            for (int ww = 0; ww < 8; ww++) {
                float4 v = *(const float4*)&s_os[nxt][ww][lane * 4];
                s.x += v.x; s.y += v.y; s.z += v.z; s.w += v.w;
            }
            const int a = lane >> 1;
            float pq[4] = {s.x, s.y, s.z, s.w};
#pragma unroll
            for (int q2 = 0; q2 < 4; q2++) {
                float on = 0.9f * oreg[q2] + 0.1f * sigf(pq[q2] + bo);
                oreg[q2] = on;
                const int b = (lane & 1) * 4 + q2;
                out[((size_t)(bg0 + b) * T_ + (t - 2)) * A_ + a] = on;
            }
        }

        // ---- o-partials for output t-1 from h_{t-1} (s_hp[cur]) ----
        if (t >= 1 && t <= T_) {
            float co[4] = {0, 0, 0, 0};
            const uint2* hp2 = (const uint2*)s_hp[cur];
#pragma unroll
            for (int i = 0; i < 2; i++) {
                const int kt = w * 2 + i;
                uint2 bb = hp2[(kt * 4 + lq) * 8 + ln];
                mma16816(co, ao[i], bb.x, bb.y);
            }
            *(float2*)&s_os[cur][w][ln * 8 + 2 * lq]      = make_float2(co[0], co[1]);
            *(float2*)&s_os[cur][w][64 + ln * 8 + 2 * lq] = make_float2(co[2], co[3]);
        }

        if (t < T_) {
            // prefetch obs(t+1)
            const int tn = (t + 1 < T_) ? t + 1 : T_ - 1;
            float2 opf = *(const float2*)
                &obs[((size_t)(bg0 + pb) * T_ + tn) * OBS_ + pk * 2];

            // ---- h-GEMM: 20 k-tiles, LDS.64 B-frags, 4 accum chains ----
            float c00[4] = {0,0,0,0}, c01[4] = {0,0,0,0};
            float c10[4] = {0,0,0,0}, c11[4] = {0,0,0,0};
            {
                const uint2* hp2 = (const uint2*)s_hp[cur];
#pragma unroll
                for (int kt = 0; kt < 16; kt++) {
                    uint2 bb = hp2[(kt * 4 + lq) * 8 + ln];
                    if (kt & 1) { mma16816(c01, ah[0][kt], bb.x, bb.y);
                                  mma16816(c11, ah[1][kt], bb.x, bb.y); }
                    else        { mma16816(c00, ah[0][kt], bb.x, bb.y);
                                  mma16816(c10, ah[1][kt], bb.x, bb.y); }
                }
                const uint2* ob2 = (const uint2*)s_ob[cur];
#pragma unroll
                for (int kt = 0; kt < 4; kt++) {
                    uint2 bb = ob2[(kt * 4 + lq) * 8 + ln];
                    if (kt & 1) { mma16816(c01, ai[0][kt], bb.x, bb.y);
                                  mma16816(c11, ai[1][kt], bb.x, bb.y); }
                    else        { mma16816(c00, ai[0][kt], bb.x, bb.y);
                                  mma16816(c10, ai[1][kt], bb.x, bb.y); }
                }
            }

            // ---- epilogue: EMA + publish h_t (fragment-order fp16) ----
            {
                uint16_t* hp16 = (uint16_t*)s_hp[nxt];
#pragma unroll
                for (int tile = 0; tile < 2; tile++) {
                    const float* ca = tile ? c10 : c00;
                    const float* cb = tile ? c11 : c01;
#pragma unroll
                    for (int e = 0; e < 4; e++) {
                        const int ri = tile * 2 + (e >> 1), par = e & 1;
                        float pre = ca[e] + cb[e] + bh[ri];
                        float hn = 0.9f * hs[ri][par] + 0.1f * sigf(pre);
                        hs[ri][par] = hn;
                        const int kt = w * 2 + (ri >> 1), ws = ri & 1;
                        const int b = 2 * lq + par;
                        hp16[((((kt * 4 + eq) * 8 + b) * 2 + ws) << 1) + ehalf] =
                            __half_as_ushort(__float2half_rn(hn));
                    }
                }
                // publish obs(t+1)
                s_ob[nxt][((okt * 4 + oq) * 8 + pb) * 2 + ows] = f2h2(opf.x, opf.y);
            }
        }

        __syncthreads();   // single barrier per step
    }

    // ---- finals (tuple order: out[B,T,A], h[1,B,H], o[1,B,A]) ----
    const size_t HOFF = (size_t)B_ * T_ * A_;
    const size_t OOFF = HOFF + (size_t)B_ * H_;
#pragma unroll
    for (int ri = 0; ri < 4; ri++) {
        const int j = jbase + 8 * ri;
#pragma unroll
        for (int par = 0; par < 2; par++) {
            const int b = 2 * lq + par;
            out[HOFF + (size_t)(bg0 + b) * H_ + j] = hs[ri][par];
        }
    }
    if (w == 0) {
        const int a = lane >> 1;
#pragma unroll
        for (int q2 = 0; q2 < 4; q2++) {
            const int b = (lane & 1) * 4 + q2;
            out[OOFF + (size_t)(bg0 + b) * A_ + a] = oreg[q2];
        }
    }
}

// ============================================================================
extern "C" void kernel_launch(void* const* d_in, const int* in_sizes, int n_in,
                              void* d_out, int out_size) {
    const float* obs   = (const float*)d_in[0];
    const float* W_in  = (const float*)d_in[1];
    const float* W_h   = (const float*)d_in[2];
    const float* b_h   = (const float*)d_in[3];
    const float* W_out = (const float*)d_in[4];
    const float* b_out = (const float*)d_in[5];
    float* out = (float*)d_out;

    rnn_kernel<<<B_ / 8, 256>>>(obs, W_in, W_h, b_h, W_out, b_out, out);
}